// round 4
// baseline (speedup 1.0000x reference)
#include <cuda_runtime.h>
#include <math.h>

#define D        128
#define NRBF     20
#define MAX_ATOMS 40960

// Scratch (alloc-free: __device__ globals)
__device__ __align__(16) float g_h[MAX_ATOMS * D];      // 20.5 MB
__device__ __align__(16) float g_agg[MAX_ATOMS * D];    // 20.5 MB
__device__ __align__(16) float g_WT[2][D * D];          // transposed W_in / W_out

__device__ __forceinline__ float ssp(float x) {
    // softplus(x) - log(2), numerically stable: max(x,0) + log1p(exp(-|x|)) - ln2
    float e = __expf(-fabsf(x));
    return fmaxf(x, 0.0f) + log1pf(e) - 0.69314718056f;
}

// Transpose W_in and W_out (row-major [c][k] -> [k][c]) so GEMM smem loads are
// coalesced and conflict-free.
__global__ void prep_kernel(const float* __restrict__ Win, const float* __restrict__ Wout) {
    int t = blockIdx.x * blockDim.x + threadIdx.x;
    if (t < D * D) {
        int c = t >> 7, k = t & 127;
        g_WT[0][k * D + c] = Win[t];
        g_WT[1][k * D + c] = Wout[t];
    }
}

__global__ void zero_kernel(int n4) {
    int t = blockIdx.x * blockDim.x + threadIdx.x;
    if (t < n4) reinterpret_cast<float4*>(g_agg)[t] = make_float4(0.f, 0.f, 0.f, 0.f);
}

// Y[r][c] = (ACT? ssp : id)( sum_k X[r][k] * W[c][k] + b[c] ), W pre-transposed in g_WT[WIDX].
// MODE 0: X = param (x), Y = g_h, no activation.
// MODE 1: X = g_agg,     Y = param (d_out), shifted-softplus.
// Block: 256 threads = 8 warps; 32 rows/block; each warp computes 4 rows,
// each lane 4 output columns (float4). K tiled by 32 through smem.
template <int MODE>
__global__ void __launch_bounds__(256) gemm_kernel(const float* __restrict__ Xparam,
                                                   const float* __restrict__ bias,
                                                   float* __restrict__ Yparam,
                                                   int n_rows) {
    __shared__ __align__(16) float sW[32 * D];   // 16 KB
    __shared__ __align__(16) float sX[32 * D];   // 16 KB

    const float* __restrict__ X = (MODE == 0) ? Xparam : g_agg;
    float* __restrict__ Y       = (MODE == 0) ? g_h    : Yparam;
    const float* __restrict__ Wt = g_WT[MODE];

    int r0 = blockIdx.x * 32;
    if (r0 >= n_rows) return;
    int lane = threadIdx.x & 31;
    int warp = threadIdx.x >> 5;

    // Load 32 input rows (coalesced)
    for (int t = threadIdx.x; t < 32 * D; t += 256) {
        int r = r0 + (t >> 7);
        sX[t] = (r < n_rows) ? X[(size_t)r * D + (t & 127)] : 0.0f;
    }

    float acc[4][4];
    #pragma unroll
    for (int r = 0; r < 4; r++)
        #pragma unroll
        for (int c = 0; c < 4; c++) acc[r][c] = 0.0f;

    #pragma unroll
    for (int tile = 0; tile < 4; tile++) {
        __syncthreads();  // first pass: covers sX; later: protects sW reuse
        for (int t = threadIdx.x; t < 32 * D; t += 256)
            sW[t] = Wt[tile * 32 * D + t];   // already [k][c]: coalesced, conflict-free
        __syncthreads();

        #pragma unroll
        for (int k = 0; k < 32; k++) {
            float4 w = *reinterpret_cast<const float4*>(sW + k * D + 4 * lane);
            #pragma unroll
            for (int r = 0; r < 4; r++) {
                float xv = sX[(warp * 4 + r) * D + tile * 32 + k];  // smem broadcast
                acc[r][0] = fmaf(w.x, xv, acc[r][0]);
                acc[r][1] = fmaf(w.y, xv, acc[r][1]);
                acc[r][2] = fmaf(w.z, xv, acc[r][2]);
                acc[r][3] = fmaf(w.w, xv, acc[r][3]);
            }
        }
    }

    float4 b4 = *reinterpret_cast<const float4*>(bias + 4 * lane);
    #pragma unroll
    for (int r = 0; r < 4; r++) {
        int row = r0 + warp * 4 + r;
        if (row < n_rows) {
            float4 o;
            o.x = acc[r][0] + b4.x;
            o.y = acc[r][1] + b4.y;
            o.z = acc[r][2] + b4.z;
            o.w = acc[r][3] + b4.w;
            if (MODE == 1) { o.x = ssp(o.x); o.y = ssp(o.y); o.z = ssp(o.z); o.w = ssp(o.w); }
            *reinterpret_cast<float4*>(Y + (size_t)row * D + 4 * lane) = o;
        }
    }
}

// Fused pair kernel: per pair p (one warp, lane owns 4 contiguous channels):
//   Wij = ssp(f_ij[p] @ W_f^T + b_f) * rcut[p]
//   agg[idx_i[p]] += h[idx_j[p]] * Wij     (red.global.add.v4.f32)
__global__ void __launch_bounds__(256) pair_kernel(const float* __restrict__ f_ij,
                                                   const int* __restrict__ idx_i,
                                                   const int* __restrict__ idx_j,
                                                   const float* __restrict__ rcut,
                                                   const float* __restrict__ W_f,
                                                   const float* __restrict__ b_f,
                                                   int n_pairs) {
    __shared__ __align__(16) float sWf[NRBF * D];  // transposed [k][c], 10 KB
    __shared__ __align__(16) float sbf[D];

    for (int t = threadIdx.x; t < NRBF * D; t += blockDim.x) {
        int c = t / NRBF, k = t - c * NRBF;
        sWf[k * D + c] = W_f[t];
    }
    if (threadIdx.x < D) sbf[threadIdx.x] = b_f[threadIdx.x];
    __syncthreads();

    int lane = threadIdx.x & 31;
    int gw   = (blockIdx.x * blockDim.x + threadIdx.x) >> 5;
    int nw   = (gridDim.x * blockDim.x) >> 5;

    const float4 b4 = *reinterpret_cast<const float4*>(sbf + 4 * lane);

    for (int p = gw; p < n_pairs; p += nw) {
        float fv = (lane < NRBF) ? f_ij[(size_t)p * NRBF + lane] : 0.0f;
        int i = idx_i[p];
        int j = idx_j[p];
        float rc = rcut[p];

        float4 acc = b4;
        #pragma unroll
        for (int k = 0; k < NRBF; k++) {
            float fk = __shfl_sync(0xffffffffu, fv, k);
            float4 w = *reinterpret_cast<const float4*>(sWf + k * D + 4 * lane);
            acc.x = fmaf(w.x, fk, acc.x);
            acc.y = fmaf(w.y, fk, acc.y);
            acc.z = fmaf(w.z, fk, acc.z);
            acc.w = fmaf(w.w, fk, acc.w);
        }
        acc.x = ssp(acc.x) * rc;
        acc.y = ssp(acc.y) * rc;
        acc.z = ssp(acc.z) * rc;
        acc.w = ssp(acc.w) * rc;

        const float4 h4 = *reinterpret_cast<const float4*>(g_h + (size_t)j * D + 4 * lane);
        float vx = h4.x * acc.x, vy = h4.y * acc.y, vz = h4.z * acc.z, vw = h4.w * acc.w;

        float* dst = g_agg + (size_t)i * D + 4 * lane;
        asm volatile("red.global.add.v4.f32 [%0], {%1,%2,%3,%4};"
                     :: "l"(dst), "f"(vx), "f"(vy), "f"(vz), "f"(vw)
                     : "memory");
    }
}

extern "C" void kernel_launch(void* const* d_in, const int* in_sizes, int n_in,
                              void* d_out, int out_size) {
    const float* x     = (const float*)d_in[0];
    const float* f_ij  = (const float*)d_in[1];
    const int*   idx_i = (const int*)  d_in[2];
    const int*   idx_j = (const int*)  d_in[3];
    const float* rcut  = (const float*)d_in[4];
    const float* W_in  = (const float*)d_in[5];
    const float* b_in  = (const float*)d_in[6];
    const float* W_f   = (const float*)d_in[7];
    const float* b_f   = (const float*)d_in[8];
    const float* W_out = (const float*)d_in[9];
    const float* b_out = (const float*)d_in[10];
    float* out = (float*)d_out;
    (void)n_in; (void)out_size;

    int n_atoms = in_sizes[0] / D;
    int n_pairs = in_sizes[2];

    // Transpose weights + zero accumulator (independent, cheap)
    prep_kernel<<<(D * D + 255) / 256, 256>>>(W_in, W_out);
    int n4 = (n_atoms * D) / 4;
    zero_kernel<<<(n4 + 255) / 256, 256>>>(n4);

    // h = x @ W_in^T + b_in   -> g_h
    int gblocks = (n_atoms + 31) / 32;
    gemm_kernel<0><<<gblocks, 256>>>(x, b_in, nullptr, n_atoms);

    // fused filter + gather + scatter-add -> g_agg  (single wave: 148 SMs * 8 blocks)
    pair_kernel<<<1184, 256>>>(f_ij, idx_i, idx_j, rcut, W_f, b_f, n_pairs);

    // out = ssp(g_agg @ W_out^T + b_out)
    gemm_kernel<1><<<gblocks, 256>>>(nullptr, b_out, out, n_atoms);
}

// round 5
// speedup vs baseline: 1.6448x; 1.6448x over previous
#include <cuda_runtime.h>
#include <math.h>

#define D        128
#define NRBF     20
#define MAX_ATOMS 40960
#define CHUNK    128   // pairs staged per block iteration

// Scratch (alloc-free: __device__ globals)
__device__ __align__(16) float g_h[MAX_ATOMS * D];      // 20.5 MB
__device__ __align__(16) float g_agg[MAX_ATOMS * D];    // 20.5 MB
__device__ __align__(16) float g_WT[2][D * D];          // transposed W_in / W_out

typedef unsigned long long ull;

__device__ __forceinline__ ull pack2(float a, float b) {
    ull r; asm("mov.b64 %0, {%1,%2};" : "=l"(r) : "f"(a), "f"(b)); return r;
}
__device__ __forceinline__ float2 unpack2(ull v) {
    float2 f; asm("mov.b64 {%0,%1}, %2;" : "=f"(f.x), "=f"(f.y) : "l"(v)); return f;
}
__device__ __forceinline__ ull ffma2(ull a, ull b, ull c) {
    ull d; asm("fma.rn.f32x2 %0, %1, %2, %3;" : "=l"(d) : "l"(a), "l"(b), "l"(c)); return d;
}

__device__ __forceinline__ float ssp(float x) {
    // softplus(x) - ln2, fast+stable: max(x,0) + log(1+exp(-|x|)) - ln2
    float e = __expf(-fabsf(x));
    return fmaxf(x, 0.0f) + __logf(1.0f + e) - 0.69314718056f;
}

// Transpose W_in / W_out ([c][k] -> [k][c]) for coalesced conflict-free GEMM tiles.
__global__ void prep_kernel(const float* __restrict__ Win, const float* __restrict__ Wout) {
    int t = blockIdx.x * blockDim.x + threadIdx.x;
    if (t < D * D) {
        int c = t >> 7, k = t & 127;
        g_WT[0][k * D + c] = Win[t];
        g_WT[1][k * D + c] = Wout[t];
    }
}

__global__ void zero_kernel(int n4) {
    int t = blockIdx.x * blockDim.x + threadIdx.x;
    if (t < n4) reinterpret_cast<float4*>(g_agg)[t] = make_float4(0.f, 0.f, 0.f, 0.f);
}

// Y[r][c] = act( sum_k X[r][k]*W[c][k] + b[c] ), W pre-transposed [k][c] in g_WT[MODE].
// MODE 0: X = x param, Y = g_h, identity. MODE 1: X = g_agg, Y = out, ssp.
// 256 threads = 8 warps; 64 rows/block; 8 rows/warp; lane owns 4 cols (2 f32x2 accs/row).
template <int MODE>
__global__ void __launch_bounds__(256) gemm_kernel(const float* __restrict__ Xparam,
                                                   const float* __restrict__ bias,
                                                   float* __restrict__ Yparam,
                                                   int n_rows) {
    __shared__ __align__(16) float sW[32 * D];   // 16 KB [k][c] tile
    __shared__ __align__(16) float sX[64 * 32];  // 8 KB  [row][k] tile

    const float* __restrict__ X  = (MODE == 0) ? Xparam : g_agg;
    float* __restrict__ Y        = (MODE == 0) ? g_h    : Yparam;
    const float* __restrict__ Wt = g_WT[MODE];

    int r0 = blockIdx.x * 64;
    if (r0 >= n_rows) return;
    int lane = threadIdx.x & 31;
    int warp = threadIdx.x >> 5;

    ull acc[8][2];
    #pragma unroll
    for (int r = 0; r < 8; r++) { acc[r][0] = 0ull; acc[r][1] = 0ull; }

    #pragma unroll
    for (int tile = 0; tile < 4; tile++) {
        __syncthreads();
        for (int t = threadIdx.x; t < 32 * D; t += 256)
            sW[t] = Wt[tile * 32 * D + t];
        for (int t = threadIdx.x; t < 512; t += 256) {   // 512 float4 = 64 rows x 32 k
            int row = t >> 3, c4 = t & 7;
            int r = r0 + row;
            float4 v = make_float4(0.f, 0.f, 0.f, 0.f);
            if (r < n_rows)
                v = *reinterpret_cast<const float4*>(X + (size_t)r * D + tile * 32 + c4 * 4);
            reinterpret_cast<float4*>(sX)[t] = v;
        }
        __syncthreads();

        #pragma unroll
        for (int k = 0; k < 32; k++) {
            ulonglong2 w = *reinterpret_cast<const ulonglong2*>(sW + k * D + 4 * lane);
            #pragma unroll
            for (int r = 0; r < 8; r++) {
                float xv = sX[(warp * 8 + r) * 32 + k];   // broadcast
                ull x2 = pack2(xv, xv);
                acc[r][0] = ffma2(w.x, x2, acc[r][0]);
                acc[r][1] = ffma2(w.y, x2, acc[r][1]);
            }
        }
    }

    float4 b4 = *reinterpret_cast<const float4*>(bias + 4 * lane);
    #pragma unroll
    for (int r = 0; r < 8; r++) {
        int row = r0 + warp * 8 + r;
        if (row < n_rows) {
            float2 p0 = unpack2(acc[r][0]);
            float2 p1 = unpack2(acc[r][1]);
            float4 o;
            o.x = p0.x + b4.x; o.y = p0.y + b4.y;
            o.z = p1.x + b4.z; o.w = p1.y + b4.w;
            if (MODE == 1) { o.x = ssp(o.x); o.y = ssp(o.y); o.z = ssp(o.z); o.w = ssp(o.w); }
            *reinterpret_cast<float4*>(Y + (size_t)row * D + 4 * lane) = o;
        }
    }
}

// Fused pair kernel v2:
//  - W_f resident in registers as packed f32x2 (lane owns 4 channels x 20 rbf)
//  - f_ij / idx / rcut block-staged in smem; f[k] read as 1-wavefront broadcast LDS
//  - h[idx_j] prefetched before the FFMA chain
//  - scatter via red.global.add.v4.f32
__global__ void __launch_bounds__(256, 2) pair_kernel(const float* __restrict__ f_ij,
                                                      const int* __restrict__ idx_i,
                                                      const int* __restrict__ idx_j,
                                                      const float* __restrict__ rcut,
                                                      const float* __restrict__ W_f,
                                                      const float* __restrict__ b_f,
                                                      int n_pairs) {
    __shared__ __align__(16) float sF[CHUNK * NRBF];  // 10 KB
    __shared__ int   sI[CHUNK];
    __shared__ int   sJ[CHUNK];
    __shared__ float sR[CHUNK];

    int lane = threadIdx.x & 31;
    int warp = threadIdx.x >> 5;

    // ---- Load this lane's 4 weight rows into packed registers (one-time) ----
    float w0[NRBF], w1[NRBF], w2[NRBF], w3[NRBF];
    {
        const float4* r0p = reinterpret_cast<const float4*>(W_f + (4 * lane + 0) * NRBF);
        const float4* r1p = reinterpret_cast<const float4*>(W_f + (4 * lane + 1) * NRBF);
        const float4* r2p = reinterpret_cast<const float4*>(W_f + (4 * lane + 2) * NRBF);
        const float4* r3p = reinterpret_cast<const float4*>(W_f + (4 * lane + 3) * NRBF);
        #pragma unroll
        for (int v = 0; v < 5; v++) {
            float4 a = r0p[v], b = r1p[v], c = r2p[v], d = r3p[v];
            w0[4*v+0]=a.x; w0[4*v+1]=a.y; w0[4*v+2]=a.z; w0[4*v+3]=a.w;
            w1[4*v+0]=b.x; w1[4*v+1]=b.y; w1[4*v+2]=b.z; w1[4*v+3]=b.w;
            w2[4*v+0]=c.x; w2[4*v+1]=c.y; w2[4*v+2]=c.z; w2[4*v+3]=c.w;
            w3[4*v+0]=d.x; w3[4*v+1]=d.y; w3[4*v+2]=d.z; w3[4*v+3]=d.w;
        }
    }
    ull wp0[NRBF], wp1[NRBF];
    #pragma unroll
    for (int k = 0; k < NRBF; k++) {
        wp0[k] = pack2(w0[k], w1[k]);
        wp1[k] = pack2(w2[k], w3[k]);
    }
    float4 bf4 = *reinterpret_cast<const float4*>(b_f + 4 * lane);
    const ull bias0 = pack2(bf4.x, bf4.y);
    const ull bias1 = pack2(bf4.z, bf4.w);

    for (int base = blockIdx.x * CHUNK; base < n_pairs; base += gridDim.x * CHUNK) {
        int cnt = min(CHUNK, n_pairs - base);
        __syncthreads();
        if (cnt == CHUNK) {
            const float4* src = reinterpret_cast<const float4*>(f_ij + (size_t)base * NRBF);
            for (int t = threadIdx.x; t < CHUNK * NRBF / 4; t += 256)
                reinterpret_cast<float4*>(sF)[t] = src[t];
        } else {
            for (int t = threadIdx.x; t < cnt * NRBF; t += 256)
                sF[t] = f_ij[(size_t)base * NRBF + t];
        }
        for (int t = threadIdx.x; t < cnt; t += 256) {
            sI[t] = idx_i[base + t];
            sJ[t] = idx_j[base + t];
            sR[t] = rcut[base + t];
        }
        __syncthreads();

        int qend = min(warp * 16 + 16, cnt);
        for (int q = warp * 16; q < qend; q++) {
            const float* f = sF + q * NRBF;
            int i = sI[q], j = sJ[q];
            float rc = sR[q];

            // prefetch neighbor features (hides L2 latency behind FFMA chain)
            const float4 h4 = *reinterpret_cast<const float4*>(g_h + (size_t)j * D + 4 * lane);

            ull a0 = bias0, a1 = bias1;
            #pragma unroll
            for (int k = 0; k < NRBF; k++) {
                float fk = f[k];                    // smem broadcast, 1 wavefront
                ull f2 = pack2(fk, fk);
                a0 = ffma2(wp0[k], f2, a0);
                a1 = ffma2(wp1[k], f2, a1);
            }
            float2 p0 = unpack2(a0);
            float2 p1 = unpack2(a1);
            float s0 = ssp(p0.x) * rc;
            float s1 = ssp(p0.y) * rc;
            float s2 = ssp(p1.x) * rc;
            float s3 = ssp(p1.y) * rc;

            float vx = h4.x * s0, vy = h4.y * s1, vz = h4.z * s2, vw = h4.w * s3;
            float* dst = g_agg + (size_t)i * D + 4 * lane;
            asm volatile("red.global.add.v4.f32 [%0], {%1,%2,%3,%4};"
                         :: "l"(dst), "f"(vx), "f"(vy), "f"(vz), "f"(vw)
                         : "memory");
        }
    }
}

extern "C" void kernel_launch(void* const* d_in, const int* in_sizes, int n_in,
                              void* d_out, int out_size) {
    const float* x     = (const float*)d_in[0];
    const float* f_ij  = (const float*)d_in[1];
    const int*   idx_i = (const int*)  d_in[2];
    const int*   idx_j = (const int*)  d_in[3];
    const float* rcut  = (const float*)d_in[4];
    const float* W_in  = (const float*)d_in[5];
    const float* b_in  = (const float*)d_in[6];
    const float* W_f   = (const float*)d_in[7];
    const float* b_f   = (const float*)d_in[8];
    const float* W_out = (const float*)d_in[9];
    const float* b_out = (const float*)d_in[10];
    float* out = (float*)d_out;
    (void)n_in; (void)out_size;

    int n_atoms = in_sizes[0] / D;
    int n_pairs = in_sizes[2];

    prep_kernel<<<(D * D + 255) / 256, 256>>>(W_in, W_out);
    int n4 = (n_atoms * D) / 4;
    zero_kernel<<<(n4 + 255) / 256, 256>>>(n4);

    int gblocks = (n_atoms + 63) / 64;
    gemm_kernel<0><<<gblocks, 256>>>(x, b_in, nullptr, n_atoms);

    pair_kernel<<<1184, 256>>>(f_ij, idx_i, idx_j, rcut, W_f, b_f, n_pairs);

    gemm_kernel<1><<<gblocks, 256>>>(nullptr, b_out, out, n_atoms);
}